// round 8
// baseline (speedup 1.0000x reference)
#include <cuda_runtime.h>
#include <cstdint>

// ---------------------------------------------------------------------------
// Self-attention, tf32 mma.sync + cp.async 2-stage pipeline, sm_100a.
// QKV proj -> exp(QK^T*scale) fused epilogue (+ per-CTA partial row sums)
// -> tiny partial-sum fold -> (attn*V)*rinv -> out = x + A*Wa + ba
// Mainloop uses a shared k-permutation so fragment loads are LDS.64.
// kernel_launch is PURE kernel launches (harness requirement).
// ---------------------------------------------------------------------------

#define BATCH 8
#define SEQ   2048
#define CDIM  512
#define UDIM  256

#define BM 128
#define BN 128
#define BK 16
#define APAD 20   // A/NT-B smem row stride (BK+4)

__device__ float g_q[BATCH * SEQ * UDIM];
__device__ float g_k[BATCH * SEQ * UDIM];
__device__ float g_v[BATCH * SEQ * UDIM];
__device__ float g_s[(long long)BATCH * SEQ * SEQ]; // exp(scores), 134 MB
__device__ float g_a[BATCH * SEQ * UDIM];
__device__ float g_psum[BATCH * SEQ * 16];          // per-colblock row sums
__device__ float g_rinv[BATCH * SEQ];

__device__ __forceinline__ void cp16(float* smem_dst, const float* gsrc) {
    const uint32_t s = (uint32_t)__cvta_generic_to_shared(smem_dst);
    asm volatile("cp.async.ca.shared.global [%0], [%1], 16;" :: "r"(s), "l"(gsrc));
}
#define CP_COMMIT() asm volatile("cp.async.commit_group;" ::: "memory")
#define CP_WAIT(n)  asm volatile("cp.async.wait_group %0;" :: "n"(n) : "memory")

__device__ __forceinline__ void mma_tf32(float (&c)[4],
                                         uint32_t a0, uint32_t a1,
                                         uint32_t a2, uint32_t a3,
                                         uint32_t b0, uint32_t b1) {
    asm volatile(
        "mma.sync.aligned.m16n8k8.row.col.f32.tf32.tf32.f32 "
        "{%0,%1,%2,%3}, {%4,%5,%6,%7}, {%8,%9}, {%0,%1,%2,%3};"
        : "+f"(c[0]), "+f"(c[1]), "+f"(c[2]), "+f"(c[3])
        : "r"(a0), "r"(a1), "r"(a2), "r"(a3), "r"(b0), "r"(b1));
}

// ---------------------------------------------------------------------------
// 128x128 tile GEMM over K, tf32 mma.sync, cp.async 2-stage pipeline.
// A: [M,K] row-major. B_NT: B is [N,K] (stored [n][k]); else [K,N]
// (stored [k][n ^ 8*((k>>1)&7)]).
//
// k-PERMUTATION: both operands map mma k-slot s to logical k as
//   s in 0..3  -> 2s ;  s in 4..7 -> 2s+1  (same bijection for A and B, so
// the dot product is exact). Consequence: each thread's (a0,a2), (a1,a3)
// and NT (b0,b1) are ADJACENT floats in smem -> single LDS.64 each.
//
// 8 warps x 64x32 warp tiles; fragment map (g=lane>>2, tig=lane&3):
//   c[0/1] -> row +g cols 2tig/2tig+1 ; c[2/3] -> row +g+8.
// ---------------------------------------------------------------------------
template <bool B_NT>
__device__ __forceinline__
void mma_tile(const float* __restrict__ A, const float* __restrict__ Bm,
              int N, int K, int mBase, int nBase,
              float (&c)[4][4][4])
{
    __shared__ float As[2][BM * APAD];
    __shared__ float Bs[2][B_NT ? (BM * APAD) : (BK * BN)];

    const int tid  = threadIdx.x;
    const int lane = tid & 31;
    const int warp = tid >> 5;
    const int wM = (warp >> 2) * 64;
    const int wN = (warp & 3) * 32;
    const int g   = lane >> 2;
    const int tig = lane & 3;

#pragma unroll
    for (int i = 0; i < 4; ++i)
#pragma unroll
        for (int j = 0; j < 4; ++j)
#pragma unroll
            for (int e = 0; e < 4; ++e) c[i][j][e] = 0.f;

    // staging coords: A / NT-B: 64 rows x 4 quads, x2 rows
    const int sRow = tid >> 2;          // 0..63
    const int sQ   = (tid & 3) * 4;     // 0,4,8,12
    // NN-B: 16 k-rows x 32 quads
    const int kR  = tid >> 4;           // 0..15
    const int nQ  = (tid & 15) * 4;     // 0..60

    const int iters = K / BK;

    auto stage = [&](int it, int buf) {
        const int kt = it * BK;
#pragma unroll
        for (int r = 0; r < 2; ++r) {
            const int row = sRow + r * 64;
            cp16(&As[buf][row * APAD + sQ],
                 &A[(long long)(mBase + row) * K + kt + sQ]);
        }
        if (B_NT) {
#pragma unroll
            for (int r = 0; r < 2; ++r) {
                const int row = sRow + r * 64;
                cp16(&Bs[buf][row * APAD + sQ],
                     &Bm[(long long)(nBase + row) * K + kt + sQ]);
            }
        } else {
            const int swz = 8 * ((kR >> 1) & 7);   // pair-swizzle (see loadB)
#pragma unroll
            for (int r = 0; r < 2; ++r) {
                const int n0 = nQ + r * 64;
                cp16(&Bs[buf][kR * BN + (n0 ^ swz)],
                     &Bm[(long long)(kt + kR) * N + nBase + n0]);
            }
        }
    };

    stage(0, 0);
    CP_COMMIT();

    for (int it = 0; it < iters; ++it) {
        const int buf = it & 1;
        if (it + 1 < iters) {
            stage(it + 1, buf ^ 1);
            CP_COMMIT();
            CP_WAIT(1);
        } else {
            CP_WAIT(0);
        }
        __syncthreads();

        const float* __restrict__ a = As[buf];
        const float* __restrict__ b = Bs[buf];

        // B fragments: register double buffer across the 2 k-steps of 8
        uint32_t bf[2][4][2];
        auto loadB = [&](int ks, int slot) {
            const int kp = ks * 8 + 2 * tig;   // logical pair base
#pragma unroll
            for (int j = 0; j < 4; ++j) {
                const int n = wN + 8 * j + g;
                if (B_NT) {
                    const float2 v = *reinterpret_cast<const float2*>(
                        &b[n * APAD + kp]);
                    bf[slot][j][0] = __float_as_uint(v.x);
                    bf[slot][j][1] = __float_as_uint(v.y);
                } else {
                    const int swz = 8 * ((kp >> 1) & 7);
                    bf[slot][j][0] = __float_as_uint(b[kp * BN + (n ^ swz)]);
                    bf[slot][j][1] = __float_as_uint(b[(kp + 1) * BN + (n ^ swz)]);
                }
            }
        };

        loadB(0, 0);
#pragma unroll
        for (int ks = 0; ks < 2; ++ks) {
            if (ks == 0) loadB(1, 1);   // overlap next B-frag LDS with MMAs
            const int kp = ks * 8 + 2 * tig;
#pragma unroll
            for (int i = 0; i < 4; ++i) {
                const int m = wM + 16 * i + g;
                const float2 va = *reinterpret_cast<const float2*>(
                    &a[m * APAD + kp]);              // (a0, a2)
                const float2 vb = *reinterpret_cast<const float2*>(
                    &a[(m + 8) * APAD + kp]);        // (a1, a3)
#pragma unroll
                for (int j = 0; j < 4; ++j)
                    mma_tf32(c[i][j],
                             __float_as_uint(va.x), __float_as_uint(vb.x),
                             __float_as_uint(va.y), __float_as_uint(vb.y),
                             bf[ks][j][0], bf[ks][j][1]);
            }
        }
        __syncthreads();
    }
}

#define EPI_COORDS                                            \
    const int lane = threadIdx.x & 31;                        \
    const int warp = threadIdx.x >> 5;                        \
    const int wM = (warp >> 2) * 64;                          \
    const int wN = (warp & 3) * 32;                           \
    const int g = lane >> 2;                                  \
    const int tig = lane & 3;

// ---------------------------------------------------------------------------
// 1) QKV projection: x[16384,512] @ W[512,256] + b; blockIdx.z picks Q/K/V.
// ---------------------------------------------------------------------------
__global__ __launch_bounds__(256, 2)
void qkv_kernel(const float* __restrict__ x,
                const float* __restrict__ Wq, const float* __restrict__ bq,
                const float* __restrict__ Wk, const float* __restrict__ bk,
                const float* __restrict__ Wv, const float* __restrict__ bv)
{
    const int which = blockIdx.z;
    const float* W    = (which == 0) ? Wq : (which == 1) ? Wk : Wv;
    const float* bias = (which == 0) ? bq : (which == 1) ? bk : bv;
    float* C          = (which == 0) ? g_q : (which == 1) ? g_k : g_v;

    const int mBase = blockIdx.y * BM;
    const int nBase = blockIdx.x * BN;

    float c[4][4][4];
    mma_tile<false>(x, W, UDIM, CDIM, mBase, nBase, c);

    EPI_COORDS
#pragma unroll
    for (int i = 0; i < 4; ++i) {
        const int r0 = mBase + wM + 16 * i + g;
#pragma unroll
        for (int j = 0; j < 4; ++j) {
            const int col = nBase + wN + 8 * j + 2 * tig;
            const float b0 = bias[col], b1 = bias[col + 1];
            float2 o0 = {c[i][j][0] + b0, c[i][j][1] + b1};
            float2 o1 = {c[i][j][2] + b0, c[i][j][3] + b1};
            *reinterpret_cast<float2*>(&C[(long long)r0 * UDIM + col]) = o0;
            *reinterpret_cast<float2*>(&C[(long long)(r0 + 8) * UDIM + col]) = o1;
        }
    }
}

// ---------------------------------------------------------------------------
// 2) g_s = exp((q @ k^T)/sqrt(U)); also writes per-CTA partial row sums to
//    g_psum[row][colBlock] (deterministic; no atomics). No max-subtraction:
//    scores are O(1), softmax is shift-invariant, fp32 exp cannot overflow.
// ---------------------------------------------------------------------------
__global__ __launch_bounds__(256, 2)
void scores_kernel()
{
    const int z = blockIdx.z;
    const float* A = g_q + (long long)z * SEQ * UDIM;
    const float* B = g_k + (long long)z * SEQ * UDIM;
    float* C       = g_s + (long long)z * SEQ * SEQ;

    const int mBase = blockIdx.y * BM;
    const int nBase = blockIdx.x * BN;

    float c[4][4][4];
    mma_tile<true>(A, B, SEQ, UDIM, mBase, nBase, c);

    __shared__ float rs[BM][4];   // [local row][column-warp]

    const float scale = 0.0625f; // 1/sqrt(256)
    EPI_COORDS
    const int wCol = warp & 3;
#pragma unroll
    for (int i = 0; i < 4; ++i) {
        const int lr0 = wM + 16 * i + g;
        const int r0  = mBase + lr0;
        float s0 = 0.f, s1 = 0.f;
#pragma unroll
        for (int j = 0; j < 4; ++j) {
            const int col = nBase + wN + 8 * j + 2 * tig;
            float2 o0 = {__expf(c[i][j][0] * scale), __expf(c[i][j][1] * scale)};
            float2 o1 = {__expf(c[i][j][2] * scale), __expf(c[i][j][3] * scale)};
            s0 += o0.x + o0.y;
            s1 += o1.x + o1.y;
            *reinterpret_cast<float2*>(&C[(long long)r0 * SEQ + col]) = o0;
            *reinterpret_cast<float2*>(&C[(long long)(r0 + 8) * SEQ + col]) = o1;
        }
        // reduce across the quad (lanes 4g..4g+3): each holds 8 of 32 cols
        s0 += __shfl_xor_sync(0xffffffffu, s0, 1);
        s0 += __shfl_xor_sync(0xffffffffu, s0, 2);
        s1 += __shfl_xor_sync(0xffffffffu, s1, 1);
        s1 += __shfl_xor_sync(0xffffffffu, s1, 2);
        if (tig == 0) {
            rs[lr0][wCol]     = s0;
            rs[lr0 + 8][wCol] = s1;
        }
    }
    __syncthreads();
    if (threadIdx.x < BM) {
        const int r = threadIdx.x;
        const float s = rs[r][0] + rs[r][1] + rs[r][2] + rs[r][3];
        g_psum[((long long)z * SEQ + mBase + r) * 16 + blockIdx.x] = s;
    }
}

// ---------------------------------------------------------------------------
// 3) Fold 16 partial sums per row -> g_rinv. 1 MB traffic.
// ---------------------------------------------------------------------------
__global__ __launch_bounds__(256)
void rinv_kernel()
{
    const int row = blockIdx.x * 256 + threadIdx.x;  // 0..16383
    const float4* p = reinterpret_cast<const float4*>(&g_psum[row * 16]);
    float s = 0.f;
#pragma unroll
    for (int i = 0; i < 4; ++i) {
        const float4 v = p[i];
        s += v.x + v.y + v.z + v.w;
    }
    g_rinv[row] = 1.0f / s;
}

// ---------------------------------------------------------------------------
// 4) a = (exp_scores @ v) * rinv[row], per batch.
// ---------------------------------------------------------------------------
__global__ __launch_bounds__(256, 2)
void av_kernel()
{
    const int z = blockIdx.z;
    const float* A = g_s + (long long)z * SEQ * SEQ;
    const float* B = g_v + (long long)z * SEQ * UDIM;
    float* C       = g_a + (long long)z * SEQ * UDIM;

    const int mBase = blockIdx.y * BM;
    const int nBase = blockIdx.x * BN;

    float c[4][4][4];
    mma_tile<false>(A, B, UDIM, SEQ, mBase, nBase, c);

    EPI_COORDS
#pragma unroll
    for (int i = 0; i < 4; ++i) {
        const int r0 = mBase + wM + 16 * i + g;
        const float rs0 = g_rinv[(long long)z * SEQ + r0];
        const float rs1 = g_rinv[(long long)z * SEQ + r0 + 8];
#pragma unroll
        for (int j = 0; j < 4; ++j) {
            const int col = nBase + wN + 8 * j + 2 * tig;
            float2 o0 = {c[i][j][0] * rs0, c[i][j][1] * rs0};
            float2 o1 = {c[i][j][2] * rs1, c[i][j][3] * rs1};
            *reinterpret_cast<float2*>(&C[(long long)r0 * UDIM + col]) = o0;
            *reinterpret_cast<float2*>(&C[(long long)(r0 + 8) * UDIM + col]) = o1;
        }
    }
}

// ---------------------------------------------------------------------------
// 5) out = x + a @ Wa + ba   [16384,256] @ [256,512]
// ---------------------------------------------------------------------------
__global__ __launch_bounds__(256, 2)
void out_kernel(const float* __restrict__ x,
                const float* __restrict__ Wa, const float* __restrict__ ba,
                float* __restrict__ out)
{
    const int mBase = blockIdx.y * BM;
    const int nBase = blockIdx.x * BN;

    float c[4][4][4];
    mma_tile<false>(g_a, Wa, CDIM, UDIM, mBase, nBase, c);

    EPI_COORDS
#pragma unroll
    for (int i = 0; i < 4; ++i) {
        const int r0 = mBase + wM + 16 * i + g;
#pragma unroll
        for (int j = 0; j < 4; ++j) {
            const int col = nBase + wN + 8 * j + 2 * tig;
            const float b0 = ba[col], b1 = ba[col + 1];
            const float2 x0 = *reinterpret_cast<const float2*>(
                &x[(long long)r0 * CDIM + col]);
            const float2 x1 = *reinterpret_cast<const float2*>(
                &x[(long long)(r0 + 8) * CDIM + col]);
            float2 o0 = {c[i][j][0] + b0 + x0.x, c[i][j][1] + b1 + x0.y};
            float2 o1 = {c[i][j][2] + b0 + x1.x, c[i][j][3] + b1 + x1.y};
            *reinterpret_cast<float2*>(&out[(long long)r0 * CDIM + col]) = o0;
            *reinterpret_cast<float2*>(&out[(long long)(r0 + 8) * CDIM + col]) = o1;
        }
    }
}

extern "C" void kernel_launch(void* const* d_in, const int* in_sizes, int n_in,
                              void* d_out, int out_size)
{
    const float* x  = (const float*)d_in[0];
    const float* Wq = (const float*)d_in[1];
    const float* bq = (const float*)d_in[2];
    const float* Wk = (const float*)d_in[3];
    const float* bk = (const float*)d_in[4];
    const float* Wv = (const float*)d_in[5];
    const float* bv = (const float*)d_in[6];
    const float* Wa = (const float*)d_in[7];
    const float* ba = (const float*)d_in[8];
    float* out = (float*)d_out;

    const dim3 blk(256);

    qkv_kernel<<<dim3(UDIM / BN, (BATCH * SEQ) / BM, 3), blk>>>(
        x, Wq, bq, Wk, bk, Wv, bv);

    scores_kernel<<<dim3(SEQ / BN, SEQ / BM, BATCH), blk>>>();

    rinv_kernel<<<(BATCH * SEQ) / 256, blk>>>();

    av_kernel<<<dim3(UDIM / BN, SEQ / BM, BATCH), blk>>>();

    out_kernel<<<dim3(CDIM / BN, (BATCH * SEQ) / BM, 1), blk>>>(x, Wa, ba, out);
}

// round 9
// speedup vs baseline: 1.1249x; 1.1249x over previous
#include <cuda_runtime.h>
#include <cstdint>

// ---------------------------------------------------------------------------
// Self-attention, tf32 mma.sync + cp.async 2-stage pipeline, sm_100a.
// QKV proj -> exp(QK^T*scale) fused epilogue (+ per-CTA partial row sums)
// -> tiny partial-sum fold -> (attn*V)*rinv -> out = x + A*Wa + ba
// Mainloop: R6-proven scalar-LDS fragment loads (APAD=20 / XOR swizzle),
// B fragments register double-buffered. kernel_launch is PURE launches.
// ---------------------------------------------------------------------------

#define BATCH 8
#define SEQ   2048
#define CDIM  512
#define UDIM  256

#define BM 128
#define BN 128
#define BK 16
#define APAD 20   // A/NT-B smem row stride (BK+4): conflict-free 4B frag reads

__device__ float g_q[BATCH * SEQ * UDIM];
__device__ float g_k[BATCH * SEQ * UDIM];
__device__ float g_v[BATCH * SEQ * UDIM];
__device__ float g_s[(long long)BATCH * SEQ * SEQ]; // exp(scores), 134 MB
__device__ float g_a[BATCH * SEQ * UDIM];
__device__ float g_psum[BATCH * SEQ * 16];          // per-colblock row sums
__device__ float g_rinv[BATCH * SEQ];

__device__ __forceinline__ void cp16(float* smem_dst, const float* gsrc) {
    const uint32_t s = (uint32_t)__cvta_generic_to_shared(smem_dst);
    asm volatile("cp.async.ca.shared.global [%0], [%1], 16;" :: "r"(s), "l"(gsrc));
}
#define CP_COMMIT() asm volatile("cp.async.commit_group;" ::: "memory")
#define CP_WAIT(n)  asm volatile("cp.async.wait_group %0;" :: "n"(n) : "memory")

__device__ __forceinline__ void mma_tf32(float (&c)[4],
                                         uint32_t a0, uint32_t a1,
                                         uint32_t a2, uint32_t a3,
                                         uint32_t b0, uint32_t b1) {
    asm volatile(
        "mma.sync.aligned.m16n8k8.row.col.f32.tf32.tf32.f32 "
        "{%0,%1,%2,%3}, {%4,%5,%6,%7}, {%8,%9}, {%0,%1,%2,%3};"
        : "+f"(c[0]), "+f"(c[1]), "+f"(c[2]), "+f"(c[3])
        : "r"(a0), "r"(a1), "r"(a2), "r"(a3), "r"(b0), "r"(b1));
}

// ---------------------------------------------------------------------------
// 128x128 tile GEMM over K, tf32 mma.sync, cp.async 2-stage pipeline.
// A: [M,K] row-major. B_NT: B is [N,K] (stored [n][k], no transpose);
// else B is [K,N] (stored [k][n^swz]).
// 8 warps, each 64x32: c[i][j] = m16n8 fragment at (wM+16i, wN+8j).
// Fragment map (g=lane>>2, tig=lane&3):
//   c[0/1] -> row +g,   cols 2tig/2tig+1 ; c[2/3] -> row +g+8.
// B fragments are register double-buffered across the 2 k-steps per tile.
// ---------------------------------------------------------------------------
template <bool B_NT>
__device__ __forceinline__
void mma_tile(const float* __restrict__ A, const float* __restrict__ Bm,
              int N, int K, int mBase, int nBase,
              float (&c)[4][4][4])
{
    __shared__ float As[2][BM * APAD];
    __shared__ float Bs[2][B_NT ? (BM * APAD) : (BK * BN)];

    const int tid  = threadIdx.x;
    const int lane = tid & 31;
    const int warp = tid >> 5;
    const int wM = (warp >> 2) * 64;
    const int wN = (warp & 3) * 32;
    const int g   = lane >> 2;
    const int tig = lane & 3;

#pragma unroll
    for (int i = 0; i < 4; ++i)
#pragma unroll
        for (int j = 0; j < 4; ++j)
#pragma unroll
            for (int e = 0; e < 4; ++e) c[i][j][e] = 0.f;

    // staging coords: A / NT-B: 64 rows x 4 quads per 256 threads, x2 rows
    const int sRow = tid >> 2;          // 0..63
    const int sQ   = (tid & 3) * 4;     // 0,4,8,12
    // NN-B: 16 k-rows x 32 quads
    const int kR  = tid >> 4;           // 0..15
    const int nQ  = (tid & 15) * 4;     // 0..60

    const int iters = K / BK;

    auto stage = [&](int it, int buf) {
        const int kt = it * BK;
#pragma unroll
        for (int r = 0; r < 2; ++r) {
            const int row = sRow + r * 64;
            cp16(&As[buf][row * APAD + sQ],
                 &A[(long long)(mBase + row) * K + kt + sQ]);
        }
        if (B_NT) {
#pragma unroll
            for (int r = 0; r < 2; ++r) {
                const int row = sRow + r * 64;
                cp16(&Bs[buf][row * APAD + sQ],
                     &Bm[(long long)(nBase + row) * K + kt + sQ]);
            }
        } else {
            const int swz = 8 * (kR & 7);
#pragma unroll
            for (int r = 0; r < 2; ++r) {
                const int n0 = nQ + r * 64;
                cp16(&Bs[buf][kR * BN + (n0 ^ swz)],
                     &Bm[(long long)(kt + kR) * N + nBase + n0]);
            }
        }
    };

    stage(0, 0);
    CP_COMMIT();

    for (int it = 0; it < iters; ++it) {
        const int buf = it & 1;
        if (it + 1 < iters) {
            stage(it + 1, buf ^ 1);
            CP_COMMIT();
            CP_WAIT(1);
        } else {
            CP_WAIT(0);
        }
        __syncthreads();

        const float* __restrict__ a = As[buf];
        const float* __restrict__ b = Bs[buf];

        // B fragments: register double buffer across the 2 k-steps of 8
        uint32_t bf[2][4][2];
        auto loadB = [&](int ks, int slot) {
            const int k0 = ks * 8;
            const int ka = k0 + tig, kb = k0 + tig + 4;
#pragma unroll
            for (int j = 0; j < 4; ++j) {
                const int n = wN + 8 * j + g;
                if (B_NT) {
                    bf[slot][j][0] = __float_as_uint(b[n * APAD + ka]);
                    bf[slot][j][1] = __float_as_uint(b[n * APAD + kb]);
                } else {
                    bf[slot][j][0] = __float_as_uint(b[ka * BN + (n ^ (8 * (ka & 7)))]);
                    bf[slot][j][1] = __float_as_uint(b[kb * BN + (n ^ (8 * (kb & 7)))]);
                }
            }
        };

        loadB(0, 0);
#pragma unroll
        for (int ks = 0; ks < 2; ++ks) {
            if (ks == 0) loadB(1, 1);   // overlap next B-frag LDS with MMAs
            const int k0 = ks * 8;
            const int ka = k0 + tig, kb = k0 + tig + 4;
#pragma unroll
            for (int i = 0; i < 4; ++i) {
                const int m = wM + 16 * i + g;
                const uint32_t a0 = __float_as_uint(a[m * APAD + ka]);
                const uint32_t a1 = __float_as_uint(a[(m + 8) * APAD + ka]);
                const uint32_t a2 = __float_as_uint(a[m * APAD + kb]);
                const uint32_t a3 = __float_as_uint(a[(m + 8) * APAD + kb]);
#pragma unroll
                for (int j = 0; j < 4; ++j)
                    mma_tf32(c[i][j], a0, a1, a2, a3,
                             bf[ks][j][0], bf[ks][j][1]);
            }
        }
        __syncthreads();
    }
}

#define EPI_COORDS                                            \
    const int lane = threadIdx.x & 31;                        \
    const int warp = threadIdx.x >> 5;                        \
    const int wM = (warp >> 2) * 64;                          \
    const int wN = (warp & 3) * 32;                           \
    const int g = lane >> 2;                                  \
    const int tig = lane & 3;

// ---------------------------------------------------------------------------
// 1) QKV projection: x[16384,512] @ W[512,256] + b; blockIdx.z picks Q/K/V.
// ---------------------------------------------------------------------------
__global__ __launch_bounds__(256, 2)
void qkv_kernel(const float* __restrict__ x,
                const float* __restrict__ Wq, const float* __restrict__ bq,
                const float* __restrict__ Wk, const float* __restrict__ bk,
                const float* __restrict__ Wv, const float* __restrict__ bv)
{
    const int which = blockIdx.z;
    const float* W    = (which == 0) ? Wq : (which == 1) ? Wk : Wv;
    const float* bias = (which == 0) ? bq : (which == 1) ? bk : bv;
    float* C          = (which == 0) ? g_q : (which == 1) ? g_k : g_v;

    const int mBase = blockIdx.y * BM;
    const int nBase = blockIdx.x * BN;

    float c[4][4][4];
    mma_tile<false>(x, W, UDIM, CDIM, mBase, nBase, c);

    EPI_COORDS
#pragma unroll
    for (int i = 0; i < 4; ++i) {
        const int r0 = mBase + wM + 16 * i + g;
#pragma unroll
        for (int j = 0; j < 4; ++j) {
            const int col = nBase + wN + 8 * j + 2 * tig;
            const float b0 = bias[col], b1 = bias[col + 1];
            float2 o0 = {c[i][j][0] + b0, c[i][j][1] + b1};
            float2 o1 = {c[i][j][2] + b0, c[i][j][3] + b1};
            *reinterpret_cast<float2*>(&C[(long long)r0 * UDIM + col]) = o0;
            *reinterpret_cast<float2*>(&C[(long long)(r0 + 8) * UDIM + col]) = o1;
        }
    }
}

// ---------------------------------------------------------------------------
// 2) g_s = exp((q @ k^T)/sqrt(U)); also writes per-CTA partial row sums to
//    g_psum[row][colBlock] (deterministic, no atomics). No max-subtraction:
//    scores are O(1), softmax is shift-invariant, fp32 exp cannot overflow.
// ---------------------------------------------------------------------------
__global__ __launch_bounds__(256, 2)
void scores_kernel()
{
    const int z = blockIdx.z;
    const float* A = g_q + (long long)z * SEQ * UDIM;
    const float* B = g_k + (long long)z * SEQ * UDIM;
    float* C       = g_s + (long long)z * SEQ * SEQ;

    const int mBase = blockIdx.y * BM;
    const int nBase = blockIdx.x * BN;

    float c[4][4][4];
    mma_tile<true>(A, B, SEQ, UDIM, mBase, nBase, c);

    __shared__ float rs[BM][4];   // [local row][column-warp]

    const float scale = 0.0625f; // 1/sqrt(256)
    EPI_COORDS
    const int wCol = warp & 3;
#pragma unroll
    for (int i = 0; i < 4; ++i) {
        const int lr0 = wM + 16 * i + g;
        const int r0  = mBase + lr0;
        float s0 = 0.f, s1 = 0.f;
#pragma unroll
        for (int j = 0; j < 4; ++j) {
            const int col = nBase + wN + 8 * j + 2 * tig;
            float2 o0 = {__expf(c[i][j][0] * scale), __expf(c[i][j][1] * scale)};
            float2 o1 = {__expf(c[i][j][2] * scale), __expf(c[i][j][3] * scale)};
            s0 += o0.x + o0.y;
            s1 += o1.x + o1.y;
            *reinterpret_cast<float2*>(&C[(long long)r0 * SEQ + col]) = o0;
            *reinterpret_cast<float2*>(&C[(long long)(r0 + 8) * SEQ + col]) = o1;
        }
        // reduce across the quad (lanes 4g..4g+3): together they cover 32 cols
        s0 += __shfl_xor_sync(0xffffffffu, s0, 1);
        s0 += __shfl_xor_sync(0xffffffffu, s0, 2);
        s1 += __shfl_xor_sync(0xffffffffu, s1, 1);
        s1 += __shfl_xor_sync(0xffffffffu, s1, 2);
        if (tig == 0) {
            rs[lr0][wCol]     = s0;
            rs[lr0 + 8][wCol] = s1;
        }
    }
    __syncthreads();
    if (threadIdx.x < BM) {
        const int r = threadIdx.x;
        const float s = rs[r][0] + rs[r][1] + rs[r][2] + rs[r][3];
        g_psum[((long long)z * SEQ + mBase + r) * 16 + blockIdx.x] = s;
    }
}

// ---------------------------------------------------------------------------
// 3) Fold 16 partial sums per row -> g_rinv. ~1 MB traffic.
// ---------------------------------------------------------------------------
__global__ __launch_bounds__(256)
void rinv_kernel()
{
    const int row = blockIdx.x * 256 + threadIdx.x;  // 0..16383
    const float4* p = reinterpret_cast<const float4*>(&g_psum[row * 16]);
    float s = 0.f;
#pragma unroll
    for (int i = 0; i < 4; ++i) {
        const float4 v = p[i];
        s += v.x + v.y + v.z + v.w;
    }
    g_rinv[row] = 1.0f / s;
}

// ---------------------------------------------------------------------------
// 4) a = (exp_scores @ v) * rinv[row], per batch.
// ---------------------------------------------------------------------------
__global__ __launch_bounds__(256, 2)
void av_kernel()
{
    const int z = blockIdx.z;
    const float* A = g_s + (long long)z * SEQ * SEQ;
    const float* B = g_v + (long long)z * SEQ * UDIM;
    float* C       = g_a + (long long)z * SEQ * UDIM;

    const int mBase = blockIdx.y * BM;
    const int nBase = blockIdx.x * BN;

    float c[4][4][4];
    mma_tile<false>(A, B, UDIM, SEQ, mBase, nBase, c);

    EPI_COORDS
#pragma unroll
    for (int i = 0; i < 4; ++i) {
        const int r0 = mBase + wM + 16 * i + g;
        const float rs0 = g_rinv[(long long)z * SEQ + r0];
        const float rs1 = g_rinv[(long long)z * SEQ + r0 + 8];
#pragma unroll
        for (int j = 0; j < 4; ++j) {
            const int col = nBase + wN + 8 * j + 2 * tig;
            float2 o0 = {c[i][j][0] * rs0, c[i][j][1] * rs0};
            float2 o1 = {c[i][j][2] * rs1, c[i][j][3] * rs1};
            *reinterpret_cast<float2*>(&C[(long long)r0 * UDIM + col]) = o0;
            *reinterpret_cast<float2*>(&C[(long long)(r0 + 8) * UDIM + col]) = o1;
        }
    }
}

// ---------------------------------------------------------------------------
// 5) out = x + a @ Wa + ba   [16384,256] @ [256,512]
// ---------------------------------------------------------------------------
__global__ __launch_bounds__(256, 2)
void out_kernel(const float* __restrict__ x,
                const float* __restrict__ Wa, const float* __restrict__ ba,
                float* __restrict__ out)
{
    const int mBase = blockIdx.y * BM;
    const int nBase = blockIdx.x * BN;

    float c[4][4][4];
    mma_tile<false>(g_a, Wa, CDIM, UDIM, mBase, nBase, c);

    EPI_COORDS
#pragma unroll
    for (int i = 0; i < 4; ++i) {
        const int r0 = mBase + wM + 16 * i + g;
#pragma unroll
        for (int j = 0; j < 4; ++j) {
            const int col = nBase + wN + 8 * j + 2 * tig;
            const float b0 = ba[col], b1 = ba[col + 1];
            const float2 x0 = *reinterpret_cast<const float2*>(
                &x[(long long)r0 * CDIM + col]);
            const float2 x1 = *reinterpret_cast<const float2*>(
                &x[(long long)(r0 + 8) * CDIM + col]);
            float2 o0 = {c[i][j][0] + b0 + x0.x, c[i][j][1] + b1 + x0.y};
            float2 o1 = {c[i][j][2] + b0 + x1.x, c[i][j][3] + b1 + x1.y};
            *reinterpret_cast<float2*>(&out[(long long)r0 * CDIM + col]) = o0;
            *reinterpret_cast<float2*>(&out[(long long)(r0 + 8) * CDIM + col]) = o1;
        }
    }
}

extern "C" void kernel_launch(void* const* d_in, const int* in_sizes, int n_in,
                              void* d_out, int out_size)
{
    const float* x  = (const float*)d_in[0];
    const float* Wq = (const float*)d_in[1];
    const float* bq = (const float*)d_in[2];
    const float* Wk = (const float*)d_in[3];
    const float* bk = (const float*)d_in[4];
    const float* Wv = (const float*)d_in[5];
    const float* bv = (const float*)d_in[6];
    const float* Wa = (const float*)d_in[7];
    const float* ba = (const float*)d_in[8];
    float* out = (float*)d_out;

    const dim3 blk(256);

    qkv_kernel<<<dim3(UDIM / BN, (BATCH * SEQ) / BM, 3), blk>>>(
        x, Wq, bq, Wk, bk, Wv, bv);

    scores_kernel<<<dim3(SEQ / BN, SEQ / BM, BATCH), blk>>>();

    rinv_kernel<<<(BATCH * SEQ) / 256, blk>>>();

    av_kernel<<<dim3(UDIM / BN, SEQ / BM, BATCH), blk>>>();

    out_kernel<<<dim3(CDIM / BN, (BATCH * SEQ) / BM, 1), blk>>>(x, Wa, ba, out);
}